// round 17
// baseline (speedup 1.0000x reference)
#include <cuda_runtime.h>
#include <cuda_fp16.h>
#include <cstdint>

// Problem constants
#define BATCH 4
#define SEQ   4096
#define DIM   1024
#define BT    (BATCH * SEQ)      // 16384

// Warp-specialized GEMM (fp16 operands, f32 accum):
// CTA tile 128x256, 9 warps: warp 8 = producer (all cp.async), warps 0-7 =
// consumers (2x4 grid of 64x64 warp tiles). 4-slot mbarrier ring; consumers
// never __syncthreads with each other in the mainloop -> no barrier convoy.
#define BM 128
#define BN 256
#define BK 32
#define NST 4
#define ASTAGE (BM * BK)                    // halves (8KB)
#define BSTAGE (BN * BK)                    // halves (16KB)
#define STAGEH (ASTAGE + BSTAGE)            // halves per stage
#define MBAR_OFF (NST * STAGEH * 2)         // byte offset of barriers
#define SMEM_DYN (MBAR_OFF + 64)            // 96KB + 8 mbarriers

// Epilogue modes
#define EPI_EXP   3
#define EPI_NORM  4
#define EPI_QKV   5

// Scratch (allocation-free rule: __device__ globals)
__device__ __half g_X [(long long)BT*DIM];
__device__ __half g_Wq[(long long)DIM*DIM];
__device__ __half g_Wk[(long long)DIM*DIM];
__device__ __half g_Wv[(long long)DIM*DIM];
__device__ __half g_Q [(long long)BT*DIM];
__device__ __half g_K [(long long)BT*DIM];
__device__ __half g_Vt[(long long)BT*DIM];         // [e][b*SEQ + t], ld = BT
__device__ __half g_P [(long long)BATCH*SEQ*SEQ];  // unnormalized exp probs, fp16
__device__ float  g_psum[64LL * BT];               // partial row sums [slot][row]
__device__ float  g_inv [BT];                      // 1 / row sum

__device__ __forceinline__ void cp16u(uint32_t saddr, const void* gm) {
    asm volatile("cp.async.cg.shared.global [%0], [%1], 16;" :: "r"(saddr), "l"(gm));
}
__device__ __forceinline__ uint32_t smem_u32(const void* p) {
    uint32_t a;
    asm("{ .reg .u64 t; cvta.to.shared.u64 t, %1; cvt.u32.u64 %0, t; }" : "=r"(a) : "l"(p));
    return a;
}
__device__ __forceinline__ void mbar_init(uint32_t a, uint32_t cnt) {
    asm volatile("mbarrier.init.shared.b64 [%0], %1;" :: "r"(a), "r"(cnt) : "memory");
}
__device__ __forceinline__ void mbar_arrive(uint32_t a) {
    asm volatile("mbarrier.arrive.shared.b64 _, [%0];" :: "r"(a) : "memory");
}
__device__ __forceinline__ void mbar_wait(uint32_t a, uint32_t parity) {
    asm volatile(
        "{\n\t.reg .pred P;\n\t"
        "W%=:\n\t"
        "mbarrier.try_wait.parity.acquire.cta.shared::cta.b64 P, [%0], %1, 0x989680;\n\t"
        "@!P bra W%=;\n\t}"
        :: "r"(a), "r"(parity) : "memory");
}
__device__ __forceinline__ void cpasync_arrive(uint32_t a) {
    asm volatile("cp.async.mbarrier.arrive.noinc.shared.b64 [%0];" :: "r"(a) : "memory");
}

#define MMA_F16(acc, a0, a1, a2, a3, b0, b1)                                \
    asm volatile(                                                           \
        "mma.sync.aligned.m16n8k16.row.col.f32.f16.f16.f32 "                \
        "{%0,%1,%2,%3}, {%4,%5,%6,%7}, {%8,%9}, {%0,%1,%2,%3};"             \
        : "+f"((acc)[0]), "+f"((acc)[1]), "+f"((acc)[2]), "+f"((acc)[3])    \
        : "r"(a0), "r"(a1), "r"(a2), "r"(a3), "r"(b0), "r"(b1))

// f32 -> f16 conversion, 4 elems/thread (x input)
__global__ void to_half_kernel(const float* __restrict__ in, __half* __restrict__ out,
                               long long n) {
    long long i = ((long long)blockIdx.x * blockDim.x + threadIdx.x) * 4;
    if (i < n) {
        float4 v = *(const float4*)(in + i);
        __half2 h0 = __floats2half2_rn(v.x, v.y);
        __half2 h1 = __floats2half2_rn(v.z, v.w);
        *(uint2*)(out + i) = make_uint2(*(uint32_t*)&h0, *(uint32_t*)&h1);
    }
}

// All three weight converts in one launch.
__global__ void w_to_half_kernel(const float* __restrict__ Wq,
                                 const float* __restrict__ Wk,
                                 const float* __restrict__ Wv) {
    int seg = blockIdx.x >> 10;
    const float* in = (seg == 0) ? Wq : (seg == 1) ? Wk : Wv;
    __half* out = (seg == 0) ? g_Wq : (seg == 1) ? g_Wk : g_Wv;
    long long i = (((long long)(blockIdx.x & 1023)) * 256 + threadIdx.x) * 4;
    float4 v = *(const float4*)(in + i);
    __half2 h0 = __floats2half2_rn(v.x, v.y);
    __half2 h1 = __floats2half2_rn(v.z, v.w);
    *(uint2*)(out + i) = make_uint2(*(uint32_t*)&h0, *(uint32_t*)&h1);
}

// Sum 64 partials per row, store reciprocal.
__global__ void rowinv_kernel(const float* __restrict__ psum, float* __restrict__ inv) {
    int row = blockIdx.x * 256 + threadIdx.x;
    float s = 0.f;
    #pragma unroll
    for (int j = 0; j < 64; j++) s += psum[(long long)j * BT + row];
    inv[row] = 1.f / s;
}

// C[M,N] = alpha * A[M,K] * B[N,K]^T, fp16 operands (K-contiguous), f32 accum.
// k-permutation trick: one LDS.128 per row gives thread tg k = {8tg..8tg+7};
// mma step0 uses {8tg..8tg+3}, step1 uses {8tg+4..8tg+7}; A/B slots agree.
template<int EPI>
__global__ void __launch_bounds__(288, 1) gemm_f16(
    const __half* __restrict__ A, const __half* __restrict__ B, void* __restrict__ Cv,
    float* __restrict__ aux,
    int lda, int ldb, int ldc,
    long long sA, long long sB, long long sC,
    int K, float alpha)
{
    extern __shared__ __half dsm[];
    const uint32_t sbase = smem_u32(dsm);
    const uint32_t mb_full  = sbase + MBAR_OFF;        // 4 x 8B
    const uint32_t mb_empty = sbase + MBAR_OFF + 32;   // 4 x 8B

    const __half* Bsel = B;
    if (EPI == EPI_QKV)
        Bsel = (blockIdx.z == 0) ? g_Wq : (blockIdx.z == 1) ? g_Wk : g_Wv;

    const __half* Ab = A + (long long)blockIdx.z * sA + (long long)blockIdx.y * BM * lda;
    const __half* Bb = Bsel + ((EPI == EPI_QKV) ? 0 : (long long)blockIdx.z * sB)
                            + (long long)blockIdx.x * BN * ldb;

    const int tid  = threadIdx.x;
    const int lane = tid & 31;
    const int warp = tid >> 5;      // 0..8

    if (tid == 0) {
        #pragma unroll
        for (int s = 0; s < NST; s++) {
            mbar_init(mb_full  + s * 8, 32);   // producer lanes (cp.async arrive)
            mbar_init(mb_empty + s * 8, 256);  // consumer threads
        }
    }
    __syncthreads();

    const int KT = K / BK;

    if (warp == 8) {
        // ---------------- Producer ----------------
        const int plr = lane >> 2;            // 0..7
        const int plc = (lane & 3) * 8;       // halves within 32-k row
        const __half* pag = Ab + (long long)plr * lda + plc;
        const __half* pbg = Bb + (long long)plr * ldb + plc;
        const uint32_t sgoff = (plr * BK + plc) * 2;   // byte offset in stage

        for (int kt = 0; kt < KT; kt++) {
            const int r = kt & 3;
            const uint32_t pphase = 1u - ((kt >> 2) & 1);
            mbar_wait(mb_empty + r * 8, pphase);

            const uint32_t sa = sbase + r * STAGEH * 2 + sgoff;
            const uint32_t sb = sa + ASTAGE * 2;
            const __half* ga = pag + kt * BK;
            const __half* gb = pbg + kt * BK;
            #pragma unroll
            for (int i = 0; i < 16; i++)            // A: 128 rows, 8/pass
                cp16u(sa + i * (8 * BK * 2), ga + (long long)(i * 8) * lda);
            #pragma unroll
            for (int i = 0; i < 32; i++)            // B: 256 rows, 8/pass
                cp16u(sb + i * (8 * BK * 2), gb + (long long)(i * 8) * ldb);

            cpasync_arrive(mb_full + r * 8);   // HW-arrives when copies land
        }
        return;   // producer skips epilogue
    }

    // ---------------- Consumers (warps 0..7) ----------------
    const int wm = warp >> 2;       // 0..1
    const int wn = warp & 3;        // 0..3
    const int g  = lane >> 2;       // 0..7
    const int tg = lane & 3;        // 0..3

    float acc[4][8][4];
    #pragma unroll
    for (int i = 0; i < 4; i++)
        #pragma unroll
        for (int j = 0; j < 8; j++)
            #pragma unroll
            for (int c = 0; c < 4; c++) acc[i][j][c] = 0.f;

    for (int kt = 0; kt < KT; kt++) {
        const int r = kt & 3;
        const uint32_t phase = (kt >> 2) & 1;
        mbar_wait(mb_full + r * 8, phase);

        const __half* as = dsm + r * STAGEH;
        const __half* bs = as + ASTAGE;

        uint4 bb[8];
        #pragma unroll
        for (int nt = 0; nt < 8; nt++)
            bb[nt] = *(const uint4*)&bs[(wn * 64 + nt * 8 + g) * BK + tg * 8];

        #pragma unroll
        for (int mt = 0; mt < 4; mt++) {
            int r0 = wm * 64 + mt * 16;
            uint4 alo = *(const uint4*)&as[(r0 + g    ) * BK + tg * 8];
            uint4 ahi = *(const uint4*)&as[(r0 + g + 8) * BK + tg * 8];
            #pragma unroll
            for (int nt = 0; nt < 8; nt++)
                MMA_F16(acc[mt][nt], alo.x, ahi.x, alo.y, ahi.y,
                        bb[nt].x, bb[nt].y);
            #pragma unroll
            for (int nt = 0; nt < 8; nt++)
                MMA_F16(acc[mt][nt], alo.z, ahi.z, alo.w, ahi.w,
                        bb[nt].z, bb[nt].w);
        }

        mbar_arrive(mb_empty + r * 8);
    }

    // ---------------- Epilogue (consumers only) ----------------
    const int zq = (EPI == EPI_QKV) ? (int)blockIdx.z : 0;
    __half* Cq = nullptr;
    int ldq = ldc;
    if (EPI == EPI_QKV) {
        Cq = (zq == 0) ? g_Q : (zq == 1) ? g_K : g_Vt;
        ldq = (zq == 2) ? BT : DIM;
    }

    #pragma unroll
    for (int mt = 0; mt < 4; mt++) {
        int row0 = blockIdx.y * BM + wm * 64 + mt * 16 + g;
        float plo = 0.f, phi = 0.f;
        float inv0 = 1.f, inv1 = 1.f;
        if (EPI == EPI_NORM) {
            const float* invp = aux + (long long)blockIdx.z * SEQ;
            inv0 = __ldg(&invp[row0]);
            inv1 = __ldg(&invp[row0 + 8]);
        }
        #pragma unroll
        for (int nt = 0; nt < 8; nt++) {
            int col0 = blockIdx.x * BN + wn * 64 + nt * 8 + 2 * tg;
            float v0 = acc[mt][nt][0] * alpha;
            float v1 = acc[mt][nt][1] * alpha;
            float v2 = acc[mt][nt][2] * alpha;
            float v3 = acc[mt][nt][3] * alpha;

            if (EPI == EPI_QKV) {
                if (zq < 2) {
                    __half2 h01 = __floats2half2_rn(v0, v1);
                    __half2 h23 = __floats2half2_rn(v2, v3);
                    *(__half2*)&Cq[(long long)(row0    ) * ldq + col0] = h01;
                    *(__half2*)&Cq[(long long)(row0 + 8) * ldq + col0] = h23;
                } else {
                    Cq[(long long)(col0    ) * ldq + row0    ] = __float2half_rn(v0);
                    Cq[(long long)(col0 + 1) * ldq + row0    ] = __float2half_rn(v1);
                    Cq[(long long)(col0    ) * ldq + row0 + 8] = __float2half_rn(v2);
                    Cq[(long long)(col0 + 1) * ldq + row0 + 8] = __float2half_rn(v3);
                }
            } else if (EPI == EPI_EXP) {
                __half* C = (__half*)Cv + (long long)blockIdx.z * sC;
                float e0 = __expf(fminf(v0, 11.f));
                float e1 = __expf(fminf(v1, 11.f));
                float e2 = __expf(fminf(v2, 11.f));
                float e3 = __expf(fminf(v3, 11.f));
                plo += e0 + e1; phi += e2 + e3;
                __half2 h01 = __floats2half2_rn(e0, e1);
                __half2 h23 = __floats2half2_rn(e2, e3);
                *(__half2*)&C[(long long)(row0    ) * ldc + col0] = h01;
                *(__half2*)&C[(long long)(row0 + 8) * ldc + col0] = h23;
            } else { // EPI_NORM
                float* C = (float*)Cv + (long long)blockIdx.z * sC;
                *(float2*)&C[(long long)(row0    ) * ldc + col0] =
                    make_float2(v0 * inv0, v1 * inv0);
                *(float2*)&C[(long long)(row0 + 8) * ldc + col0] =
                    make_float2(v2 * inv1, v3 * inv1);
            }
        }
        if (EPI == EPI_EXP) {
            plo += __shfl_xor_sync(0xffffffffu, plo, 1);
            plo += __shfl_xor_sync(0xffffffffu, plo, 2);
            phi += __shfl_xor_sync(0xffffffffu, phi, 1);
            phi += __shfl_xor_sync(0xffffffffu, phi, 2);
            if (tg == 0) {
                long long slot = (long long)(blockIdx.x * 4 + wn) * BT
                               + (long long)blockIdx.z * SEQ;
                aux[slot + row0    ] = plo;
                aux[slot + row0 + 8] = phi;
            }
        }
    }
}

extern "C" void kernel_launch(void* const* d_in, const int* in_sizes, int n_in,
                              void* d_out, int out_size) {
    const float* x  = (const float*)d_in[0];
    const float* Wq = (const float*)d_in[1];
    const float* Wk = (const float*)d_in[2];
    const float* Wv = (const float*)d_in[3];
    float* out = (float*)d_out;

    __half *pX, *pQ, *pK, *pVt, *pP;
    float *pPsum, *pInv;
    cudaGetSymbolAddress((void**)&pX,  g_X);
    cudaGetSymbolAddress((void**)&pQ,  g_Q);
    cudaGetSymbolAddress((void**)&pK,  g_K);
    cudaGetSymbolAddress((void**)&pVt, g_Vt);
    cudaGetSymbolAddress((void**)&pP,  g_P);
    cudaGetSymbolAddress((void**)&pPsum, g_psum);
    cudaGetSymbolAddress((void**)&pInv,  g_inv);

    cudaFuncSetAttribute(gemm_f16<EPI_QKV >, cudaFuncAttributeMaxDynamicSharedMemorySize, SMEM_DYN);
    cudaFuncSetAttribute(gemm_f16<EPI_EXP >, cudaFuncAttributeMaxDynamicSharedMemorySize, SMEM_DYN);
    cudaFuncSetAttribute(gemm_f16<EPI_NORM>, cudaFuncAttributeMaxDynamicSharedMemorySize, SMEM_DYN);

    const long long nX = (long long)BT * DIM;
    const long long strideQK = (long long)SEQ * DIM;
    const long long strideS  = (long long)SEQ * SEQ;

    // Convert inputs to fp16
    to_half_kernel<<<(unsigned)(nX / 4 / 256), 256>>>(x, pX, nX);
    w_to_half_kernel<<<3 * 1024, 256>>>(Wq, Wk, Wv);

    // Fused QKV projections: one launch, z selects weight + destination.
    dim3 gProj(DIM / BN, BT / BM, 3);
    gemm_f16<EPI_QKV><<<gProj, 288, SMEM_DYN>>>(pX, nullptr, nullptr, nullptr,
                                                DIM, DIM, DIM, 0, 0, 0, DIM, 1.0f);

    // Scores + exp fused: P_b = exp(Q_b K_b^T / 32), partial row sums to psum
    dim3 gS(SEQ / BN, SEQ / BM, BATCH);
    gemm_f16<EPI_EXP><<<gS, 288, SMEM_DYN>>>(pQ, pK, pP, pPsum, DIM, DIM, SEQ,
                                             strideQK, strideQK, strideS, DIM, 0.03125f);

    // Row sums -> reciprocals
    rowinv_kernel<<<BT / 256, 256>>>(pPsum, pInv);

    // Output: O_b = (P_b V_b) * inv_rowsum -> f32
    dim3 gO(DIM / BN, SEQ / BM, BATCH);
    gemm_f16<EPI_NORM><<<gO, 288, SMEM_DYN>>>(pP, pVt, out, pInv, SEQ, BT, DIM,
                                              strideS, (long long)SEQ, (long long)SEQ * DIM,
                                              SEQ, 1.0f);
}